// round 7
// baseline (speedup 1.0000x reference)
#include <cuda_runtime.h>
#include <math.h>

#define Hd 512
#define SEQ 2048
#define G4 2048            // 4*H
#define NTAGS 81
#define START_TAG 79
#define STOP_TAG 80
#define NEGV -10000.0f
#define NCTA_DIR 64
#define REC_CTAS (2*NCTA_DIR)
#define NWARP_DIR (NCTA_DIR*8)   // 512 arrivals per step per direction

// ---------------- scratch (device globals: no allocation allowed) ----------
__device__ float g_U[2][SEQ][G4];        // x @ Wih^T (no biases), 32MB
__device__ float g_X[SEQ][Hd];           // gathered embeddings
__device__ float g_hseq[2][SEQ][Hd];     // hidden states
__device__ unsigned g_cnt[2][SEQ];       // per-step arrival counters (512 each)
__device__ float g_feats[SEQ][NTAGS];
__device__ float g_fv2[SEQ][NTAGS];      // viterbi step_vars history

// ---------------- reset (graph replays must be deterministic) --------------
__global__ void reset_kernel() {
    int i = blockIdx.x * blockDim.x + threadIdx.x;
    if (i < 2 * SEQ) ((unsigned*)g_cnt)[i] = 0u;
}

// ---------------- embedding gather -----------------------------------------
__global__ void gather_kernel(const int* __restrict__ sentence,
                              const float* __restrict__ emb) {
    int t = blockIdx.x;
    int idx = sentence[t];
    const float4* src = (const float4*)(emb + (size_t)idx * Hd);
    ((float4*)(g_X[t]))[threadIdx.x] = src[threadIdx.x];   // 128 * float4 = 512
}

// ---------------- input projection GEMM (fp32): U = X · Wih^T --------------
#define BM 64
#define BN 64
#define BK 16
__global__ __launch_bounds__(256) void gemm_kernel(
    const float* __restrict__ Wih_f, const float* __restrict__ Wih_b) {
    int dir = blockIdx.z;
    const float* W = dir ? Wih_b : Wih_f;
    int t0 = blockIdx.y * BM;
    int r0 = blockIdx.x * BN;

    __shared__ float As[BK][BM + 1];
    __shared__ float Bs[BK][BN + 1];
    int tid = threadIdx.x;
    int tx = tid & 15, ty = tid >> 4;

    float acc[4][4];
#pragma unroll
    for (int i = 0; i < 4; i++)
#pragma unroll
        for (int j = 0; j < 4; j++) acc[i][j] = 0.f;

    for (int kk = 0; kk < Hd; kk += BK) {
#pragma unroll
        for (int i = 0; i < 4; i++) {
            int lin = i * 256 + tid;
            int m = lin >> 4, k = lin & 15;
            As[k][m] = g_X[t0 + m][kk + k];
            Bs[k][m] = W[(size_t)(r0 + m) * Hd + kk + k];
        }
        __syncthreads();
#pragma unroll
        for (int k = 0; k < BK; k++) {
            float a[4], b[4];
#pragma unroll
            for (int i = 0; i < 4; i++) a[i] = As[k][ty * 4 + i];
#pragma unroll
            for (int j = 0; j < 4; j++) b[j] = Bs[k][tx * 4 + j];
#pragma unroll
            for (int i = 0; i < 4; i++)
#pragma unroll
                for (int j = 0; j < 4; j++) acc[i][j] += a[i] * b[j];
        }
        __syncthreads();
    }
#pragma unroll
    for (int i = 0; i < 4; i++) {
        int t = t0 + ty * 4 + i;
        int r = r0 + tx * 4;
        *(float4*)&g_U[dir][t][r] = make_float4(acc[i][0], acc[i][1], acc[i][2], acc[i][3]);
    }
}

// ---------------- recurrent LSTM (persistent, per-warp release/acquire) ----
__device__ __forceinline__ unsigned ld_acq(const unsigned* p) {
    unsigned v;
    asm volatile("ld.acquire.gpu.global.u32 %0, [%1];" : "=r"(v) : "l"(p) : "memory");
    return v;
}
__device__ __forceinline__ void red_release(unsigned* p) {
    asm volatile("red.add.release.gpu.global.u32 [%0], 1;" :: "l"(p) : "memory");
}
__device__ __forceinline__ void st_cg(float* p, float v) {
    asm volatile("st.global.cg.f32 [%0], %1;" :: "l"(p), "f"(v) : "memory");
}

__global__ __launch_bounds__(256, 1) void lstm_kernel(
    const float* __restrict__ h0, const float* __restrict__ c0,
    const float* __restrict__ Whh_f, const float* __restrict__ Whh_b,
    const float* __restrict__ bih_f, const float* __restrict__ bhh_f,
    const float* __restrict__ bih_b, const float* __restrict__ bhh_b) {
    int dir = (blockIdx.x >= NCTA_DIR) ? 1 : 0;
    int cta = blockIdx.x - dir * NCTA_DIR;
    const float* Whh = dir ? Whh_b : Whh_f;
    const float* bih = dir ? bih_b : bih_f;
    const float* bhh = dir ? bhh_b : bhh_f;
    int warp = threadIdx.x >> 5, lane = threadIdx.x & 31;
    int unit = cta * 8 + warp;       // 8 warps, one hidden unit each

    // weights resident in registers (pure fp32)
    float w0[16], w1[16], w2[16], w3[16];
    {
        const float* r0 = Whh + (size_t)unit * Hd;
        const float* r1 = Whh + (size_t)(unit + Hd) * Hd;
        const float* r2 = Whh + (size_t)(unit + 2 * Hd) * Hd;
        const float* r3 = Whh + (size_t)(unit + 3 * Hd) * Hd;
#pragma unroll
        for (int k = 0; k < 16; k++) {
            w0[k] = r0[k * 32 + lane];
            w1[k] = r1[k * 32 + lane];
            w2[k] = r2[k * 32 + lane];
            w3[k] = r3[k * 32 + lane];
        }
    }

    float bi0 = 0.f, bi1 = 0.f, bi2 = 0.f, bi3 = 0.f;
    float bh0 = 0.f, bh1 = 0.f, bh2 = 0.f, bh3 = 0.f;
    float c = 0.f;
    if (lane == 0) {
        bi0 = bih[unit];            bh0 = bhh[unit];
        bi1 = bih[unit + Hd];       bh1 = bhh[unit + Hd];
        bi2 = bih[unit + 2 * Hd];   bh2 = bhh[unit + 2 * Hd];
        bi3 = bih[unit + 3 * Hd];   bh3 = bhh[unit + 3 * Hd];
        c = c0[dir * Hd + unit];
    }

    __shared__ float h_sh[Hd];

    for (int s = 0; s < SEQ; s++) {
        int t = dir ? (SEQ - 1 - s) : s;

        // prefetch U (g_U is constant during this kernel — safe before sync)
        float u0 = 0.f, u1 = 0.f, u2 = 0.f, u3 = 0.f;
        if (lane == 0) {
            const float* u = &g_U[dir][t][0];
            u0 = u[unit];
            u1 = u[unit + Hd];
            u2 = u[unit + 2 * Hd];
            u3 = u[unit + 3 * Hd];
        }

        const float* hsrc;
        if (s == 0) {
            hsrc = h0 + dir * Hd;
        } else {
            int tp = dir ? t + 1 : t - 1;
            const unsigned* cp = &g_cnt[dir][tp];
            if (lane == 0) {
                while (ld_acq(cp) < NWARP_DIR) {}
            }
            __syncwarp();
            (void)ld_acq(cp);   // per-lane acquire: release-sequence of RMWs
                                // => every lane synchronizes-with all writers
            hsrc = &g_hseq[dir][tp][0];
        }
        __syncthreads();                       // h_sh writers vs prev readers
        h_sh[threadIdx.x]       = __ldcg(&hsrc[threadIdx.x]);   // L2 path only
        h_sh[threadIdx.x + 256] = __ldcg(&hsrc[threadIdx.x + 256]);
        __syncthreads();

        float a0 = 0.f, a1 = 0.f, a2 = 0.f, a3 = 0.f;
#pragma unroll
        for (int k = 0; k < 16; k++) {
            float hv = h_sh[k * 32 + lane];
            a0 += w0[k] * hv;
            a1 += w1[k] * hv;
            a2 += w2[k] * hv;
            a3 += w3[k] * hv;
        }
#pragma unroll
        for (int off = 16; off > 0; off >>= 1) {
            a0 += __shfl_xor_sync(0xffffffffu, a0, off);
            a1 += __shfl_xor_sync(0xffffffffu, a1, off);
            a2 += __shfl_xor_sync(0xffffffffu, a2, off);
            a3 += __shfl_xor_sync(0xffffffffu, a3, off);
        }
        if (lane == 0) {
            // g = ((xW + hW) + bih) + bhh  -- reference add order, no FMA fusion
            float gi = __fadd_rn(__fadd_rn(__fadd_rn(u0, a0), bi0), bh0);
            float gf = __fadd_rn(__fadd_rn(__fadd_rn(u1, a1), bi1), bh1);
            float gg = __fadd_rn(__fadd_rn(__fadd_rn(u2, a2), bi2), bh2);
            float go = __fadd_rn(__fadd_rn(__fadd_rn(u3, a3), bi3), bh3);
            float i_ = 1.f / (1.f + expf(-gi));
            float f_ = 1.f / (1.f + expf(-gf));
            float o_ = 1.f / (1.f + expf(-go));
            c = __fadd_rn(__fmul_rn(f_, c), __fmul_rn(i_, tanhf(gg)));
            float h2 = __fmul_rn(o_, tanhf(c));
            st_cg(&g_hseq[dir][t][unit], h2);   // bypass L1
            red_release(&g_cnt[dir][t]);        // same-thread release: airtight
        }
        // no end-of-step CTA barrier needed: next iteration's __syncthreads
        // separates h_sh rewrite from this step's readers
    }
}

// ---------------- feats: concat(hf,hb) @ Wt^T + bt (fp32) -------------------
__global__ __launch_bounds__(256) void feats_kernel(const float* __restrict__ Wt,
                                                    const float* __restrict__ bt) {
    int t = blockIdx.x;
    __shared__ float hc[2 * Hd];
    int tid = threadIdx.x;
#pragma unroll
    for (int i = 0; i < 4; i++) {
        int j = tid + i * 256;
        hc[j] = (j < Hd) ? g_hseq[0][t][j] : g_hseq[1][t][j - Hd];
    }
    __syncthreads();
    int warp = tid >> 5, lane = tid & 31;
    for (int n = warp; n < NTAGS; n += 8) {
        const float* w = Wt + (size_t)n * 2 * Hd;
        float s = 0.f;
#pragma unroll
        for (int k = lane; k < 2 * Hd; k += 32) s += w[k] * hc[k];
#pragma unroll
        for (int off = 16; off > 0; off >>= 1) s += __shfl_xor_sync(0xffffffffu, s, off);
        if (lane == 0) g_feats[t][n] = __fadd_rn(s, bt[n]);
    }
}

// ---------------- viterbi (single CTA, SMEM-resident backpointers) ---------
#define VIT_SMEM (NTAGS*NTAGS*4 + 2*96*4 + 16 + SEQ*NTAGS)

__global__ void viterbi_kernel(const float* __restrict__ trans, float* __restrict__ out,
                               int out_size) {
    extern __shared__ char smraw[];
    float* trs = (float*)smraw;                                   // 81*81
    float* fv  = (float*)(smraw + NTAGS * NTAGS * 4);             // 2*96 (double buffer)
    int*   sh_best = (int*)(smraw + NTAGS * NTAGS * 4 + 2 * 96 * 4);
    unsigned char* bp = (unsigned char*)(smraw + NTAGS * NTAGS * 4 + 2 * 96 * 4 + 16);
    int tid = threadIdx.x;

    for (int i = tid; i < NTAGS * NTAGS; i += 128) trs[i] = trans[i];
    if (tid < NTAGS) fv[tid] = (tid == START_TAG) ? 0.f : NEGV;
    __syncthreads();

    int cur = 0;
    for (int t = 0; t < SEQ; t++) {
        if (tid < NTAGS) {
            float feat = g_feats[t][tid];
            const float* tr = trs + tid * NTAGS;
            const float* f = fv + cur * 96;
            float b0 = -3.4e38f, b1 = -3.4e38f, b2 = -3.4e38f, b3 = -3.4e38f;
            int i0 = 0, i1 = 1, i2 = 2, i3 = 3;
#pragma unroll
            for (int j = 0; j < 80; j += 4) {
                float v0 = __fadd_rn(f[j], tr[j]);         if (v0 > b0) { b0 = v0; i0 = j; }
                float v1 = __fadd_rn(f[j + 1], tr[j + 1]); if (v1 > b1) { b1 = v1; i1 = j + 1; }
                float v2 = __fadd_rn(f[j + 2], tr[j + 2]); if (v2 > b2) { b2 = v2; i2 = j + 2; }
                float v3 = __fadd_rn(f[j + 3], tr[j + 3]); if (v3 > b3) { b3 = v3; i3 = j + 3; }
            }
            { float v = __fadd_rn(f[80], tr[80]); if (v > b0) { b0 = v; i0 = 80; } }
            // combine, first-index tie-break (matches jnp.argmax)
            float bb = b0; int bi = i0;
            if (b1 > bb || (b1 == bb && i1 < bi)) { bb = b1; bi = i1; }
            if (b2 > bb || (b2 == bb && i2 < bi)) { bb = b2; bi = i2; }
            if (b3 > bb || (b3 == bb && i3 < bi)) { bb = b3; bi = i3; }
            bp[t * NTAGS + tid] = (unsigned char)bi;
            float nv = __fadd_rn(bb, feat);
            fv[(cur ^ 1) * 96 + tid] = nv;
            g_fv2[t][tid] = nv;
        }
        __syncthreads();
        cur ^= 1;
    }

    if (tid == 0) {
        const float* f = fv + cur * 96;
        float best = -3.4e38f; int bi = 0;
        for (int i = 0; i < NTAGS; i++) {
            float v = __fadd_rn(f[i], trs[STOP_TAG * NTAGS + i]);
            if (v > best) { best = v; bi = i; }
        }
        if (out_size > 0) out[0] = best;       // path_score
        sh_best[0] = bi;
        int tag = bi;
        for (int t = SEQ - 1; t >= 0; t--) {   // backtrace in SMEM
            if (1 + t < out_size) out[1 + t] = (float)tag;
            tag = bp[t * NTAGS + tag];
        }
    }
    __syncthreads();
    int best = sh_best[0];
    for (int k = tid; k < SEQ; k += 128) {
        int idx = 1 + SEQ + k;
        if (idx < out_size) out[idx] = g_fv2[SEQ - 1 - k][best];  // best_tag_score
    }
}

// ---------------- launch -----------------------------------------------------
extern "C" void kernel_launch(void* const* d_in, const int* in_sizes, int n_in,
                              void* d_out, int out_size) {
    const int*   sentence = (const int*)d_in[0];
    const float* h0    = (const float*)d_in[1];
    const float* c0    = (const float*)d_in[2];
    const float* emb   = (const float*)d_in[3];
    const float* Wih_f = (const float*)d_in[4];
    const float* Whh_f = (const float*)d_in[5];
    const float* bih_f = (const float*)d_in[6];
    const float* bhh_f = (const float*)d_in[7];
    const float* Wih_b = (const float*)d_in[8];
    const float* Whh_b = (const float*)d_in[9];
    const float* bih_b = (const float*)d_in[10];
    const float* bhh_b = (const float*)d_in[11];
    const float* Wt    = (const float*)d_in[12];
    const float* bt    = (const float*)d_in[13];
    const float* trans = (const float*)d_in[14];
    float* out = (float*)d_out;

    reset_kernel<<<(2 * SEQ + 255) / 256, 256>>>();
    gather_kernel<<<SEQ, 128>>>(sentence, emb);
    dim3 gg(G4 / BN, SEQ / BM, 2);
    gemm_kernel<<<gg, 256>>>(Wih_f, Wih_b);
    lstm_kernel<<<REC_CTAS, 256>>>(h0, c0, Whh_f, Whh_b, bih_f, bhh_f, bih_b, bhh_b);
    feats_kernel<<<SEQ, 256>>>(Wt, bt);
    cudaFuncSetAttribute(viterbi_kernel, cudaFuncAttributeMaxDynamicSharedMemorySize, VIT_SMEM);
    viterbi_kernel<<<1, 128, VIT_SMEM>>>(trans, out, out_size);
}

// round 9
// speedup vs baseline: 1.1649x; 1.1649x over previous
#include <cuda_runtime.h>
#include <math.h>

#define Hd 512
#define SEQ 2048
#define NTAGS 81
#define START_TAG 79
#define STOP_TAG 80
#define NEGV -10000.0f
#define NCTA_DIR 64
#define REC_CTAS (2*NCTA_DIR)
#define NWARP_DIR (NCTA_DIR*8)   // 512 arrivals per step per direction

// ---------------- scratch (device globals: no allocation allowed) ----------
__device__ float g_X[SEQ][Hd];           // gathered embeddings
__device__ float g_hseq[2][SEQ][Hd];     // hidden states
__device__ unsigned g_cnt[2][SEQ];       // per-step arrival counters (512 each)
__device__ float g_feats[SEQ][NTAGS];
__device__ float g_fv2[SEQ][NTAGS];      // viterbi step_vars history

// ---------------- reset (graph replays must be deterministic) --------------
__global__ void reset_kernel() {
    int i = blockIdx.x * blockDim.x + threadIdx.x;
    if (i < 2 * SEQ) ((unsigned*)g_cnt)[i] = 0u;
}

// ---------------- embedding gather -----------------------------------------
__global__ void gather_kernel(const int* __restrict__ sentence,
                              const float* __restrict__ emb) {
    int t = blockIdx.x;
    int idx = sentence[t];
    const float4* src = (const float4*)(emb + (size_t)idx * Hd);
    ((float4*)(g_X[t]))[threadIdx.x] = src[threadIdx.x];   // 128 * float4 = 512
}

// ---------------- recurrent LSTM (persistent, per-warp release/acquire) ----
// Sync protocol identical to the round-7 PASSING kernel. Only the u-computation
// changed (register-resident Wih, replaces the separate GEMM).
__device__ __forceinline__ unsigned ld_acq(const unsigned* p) {
    unsigned v;
    asm volatile("ld.acquire.gpu.global.u32 %0, [%1];" : "=r"(v) : "l"(p) : "memory");
    return v;
}
__device__ __forceinline__ void red_release(unsigned* p) {
    asm volatile("red.add.release.gpu.global.u32 [%0], 1;" :: "l"(p) : "memory");
}
__device__ __forceinline__ void st_cg(float* p, float v) {
    asm volatile("st.global.cg.f32 [%0], %1;" :: "l"(p), "f"(v) : "memory");
}

__global__ __launch_bounds__(256, 1) void lstm_kernel(
    const float* __restrict__ h0, const float* __restrict__ c0,
    const float* __restrict__ Whh_f, const float* __restrict__ Whh_b,
    const float* __restrict__ Wih_f, const float* __restrict__ Wih_b,
    const float* __restrict__ bih_f, const float* __restrict__ bhh_f,
    const float* __restrict__ bih_b, const float* __restrict__ bhh_b) {
    int dir = (blockIdx.x >= NCTA_DIR) ? 1 : 0;
    int cta = blockIdx.x - dir * NCTA_DIR;
    const float* Whh = dir ? Whh_b : Whh_f;
    const float* Wih = dir ? Wih_b : Wih_f;
    const float* bih = dir ? bih_b : bih_f;
    const float* bhh = dir ? bhh_b : bhh_f;
    int warp = threadIdx.x >> 5, lane = threadIdx.x & 31;
    int unit = cta * 8 + warp;       // 8 warps, one hidden unit each

    // recurrent + input weights resident in registers (4 gate rows each)
    float wh0[16], wh1[16], wh2[16], wh3[16];
    float wx0[16], wx1[16], wx2[16], wx3[16];
    {
        const float* r0 = Whh + (size_t)unit * Hd;
        const float* r1 = Whh + (size_t)(unit + Hd) * Hd;
        const float* r2 = Whh + (size_t)(unit + 2 * Hd) * Hd;
        const float* r3 = Whh + (size_t)(unit + 3 * Hd) * Hd;
        const float* q0 = Wih + (size_t)unit * Hd;
        const float* q1 = Wih + (size_t)(unit + Hd) * Hd;
        const float* q2 = Wih + (size_t)(unit + 2 * Hd) * Hd;
        const float* q3 = Wih + (size_t)(unit + 3 * Hd) * Hd;
#pragma unroll
        for (int k = 0; k < 16; k++) {
            wh0[k] = r0[k * 32 + lane];
            wh1[k] = r1[k * 32 + lane];
            wh2[k] = r2[k * 32 + lane];
            wh3[k] = r3[k * 32 + lane];
            wx0[k] = q0[k * 32 + lane];
            wx1[k] = q1[k * 32 + lane];
            wx2[k] = q2[k * 32 + lane];
            wx3[k] = q3[k * 32 + lane];
        }
    }

    float bi0 = 0.f, bi1 = 0.f, bi2 = 0.f, bi3 = 0.f;
    float bh0 = 0.f, bh1 = 0.f, bh2 = 0.f, bh3 = 0.f;
    float c = 0.f;
    if (lane == 0) {
        bi0 = bih[unit];            bh0 = bhh[unit];
        bi1 = bih[unit + Hd];       bh1 = bhh[unit + Hd];
        bi2 = bih[unit + 2 * Hd];   bh2 = bhh[unit + 2 * Hd];
        bi3 = bih[unit + 3 * Hd];   bh3 = bhh[unit + 3 * Hd];
        c = c0[dir * Hd + unit];
    }

    __shared__ float h_sh[Hd];

    for (int s = 0; s < SEQ; s++) {
        int t = dir ? (SEQ - 1 - s) : s;

        // ---- u = x_t · Wih rows, from registers + coalesced __ldg of g_X.
        // Computed BEFORE the spin: hides in the previous step's store flight.
        float u0 = 0.f, u1 = 0.f, u2 = 0.f, u3 = 0.f;
        {
            const float* xp = &g_X[t][0];
#pragma unroll
            for (int k = 0; k < 16; k++) {
                float xv = __ldg(xp + k * 32 + lane);
                u0 += wx0[k] * xv;
                u1 += wx1[k] * xv;
                u2 += wx2[k] * xv;
                u3 += wx3[k] * xv;
            }
#pragma unroll
            for (int off = 16; off > 0; off >>= 1) {
                u0 += __shfl_xor_sync(0xffffffffu, u0, off);
                u1 += __shfl_xor_sync(0xffffffffu, u1, off);
                u2 += __shfl_xor_sync(0xffffffffu, u2, off);
                u3 += __shfl_xor_sync(0xffffffffu, u3, off);
            }
        }

        // ---- acquire h_{t-1}: EXACT round-7 protocol ----
        const float* hsrc;
        if (s == 0) {
            hsrc = h0 + dir * Hd;
        } else {
            int tp = dir ? t + 1 : t - 1;
            const unsigned* cp = &g_cnt[dir][tp];
            if (lane == 0) {
                while (ld_acq(cp) < NWARP_DIR) {}
            }
            __syncwarp();
            (void)ld_acq(cp);   // per-lane acquire: release-sequence of RMWs
                                // => every lane synchronizes-with all writers
            hsrc = &g_hseq[dir][tp][0];
        }
        __syncthreads();                       // h_sh writers vs prev readers
        h_sh[threadIdx.x]       = __ldcg(&hsrc[threadIdx.x]);   // L2 path only
        h_sh[threadIdx.x + 256] = __ldcg(&hsrc[threadIdx.x + 256]);
        __syncthreads();

        // ---- a = h_{t-1} · Whh rows
        float a0 = 0.f, a1 = 0.f, a2 = 0.f, a3 = 0.f;
#pragma unroll
        for (int k = 0; k < 16; k++) {
            float hv = h_sh[k * 32 + lane];
            a0 += wh0[k] * hv;
            a1 += wh1[k] * hv;
            a2 += wh2[k] * hv;
            a3 += wh3[k] * hv;
        }
#pragma unroll
        for (int off = 16; off > 0; off >>= 1) {
            a0 += __shfl_xor_sync(0xffffffffu, a0, off);
            a1 += __shfl_xor_sync(0xffffffffu, a1, off);
            a2 += __shfl_xor_sync(0xffffffffu, a2, off);
            a3 += __shfl_xor_sync(0xffffffffu, a3, off);
        }
        if (lane == 0) {
            // g = ((xW + hW) + bih) + bhh  -- reference add order, no FMA fusion
            float gi = __fadd_rn(__fadd_rn(__fadd_rn(u0, a0), bi0), bh0);
            float gf = __fadd_rn(__fadd_rn(__fadd_rn(u1, a1), bi1), bh1);
            float gg = __fadd_rn(__fadd_rn(__fadd_rn(u2, a2), bi2), bh2);
            float go = __fadd_rn(__fadd_rn(__fadd_rn(u3, a3), bi3), bh3);
            float i_ = 1.f / (1.f + expf(-gi));
            float f_ = 1.f / (1.f + expf(-gf));
            float o_ = 1.f / (1.f + expf(-go));
            c = __fadd_rn(__fmul_rn(f_, c), __fmul_rn(i_, tanhf(gg)));
            float h2 = __fmul_rn(o_, tanhf(c));
            st_cg(&g_hseq[dir][t][unit], h2);   // bypass L1
            red_release(&g_cnt[dir][t]);        // same-thread release: airtight
        }
    }
}

// ---------------- feats: concat(hf,hb) @ Wt^T + bt (fp32) -------------------
__global__ __launch_bounds__(256) void feats_kernel(const float* __restrict__ Wt,
                                                    const float* __restrict__ bt) {
    int t = blockIdx.x;
    __shared__ float hc[2 * Hd];
    int tid = threadIdx.x;
#pragma unroll
    for (int i = 0; i < 4; i++) {
        int j = tid + i * 256;
        hc[j] = (j < Hd) ? g_hseq[0][t][j] : g_hseq[1][t][j - Hd];
    }
    __syncthreads();
    int warp = tid >> 5, lane = tid & 31;
    for (int n = warp; n < NTAGS; n += 8) {
        const float* w = Wt + (size_t)n * 2 * Hd;
        float s = 0.f;
#pragma unroll
        for (int k = lane; k < 2 * Hd; k += 32) s += w[k] * hc[k];
#pragma unroll
        for (int off = 16; off > 0; off >>= 1) s += __shfl_xor_sync(0xffffffffu, s, off);
        if (lane == 0) g_feats[t][n] = __fadd_rn(s, bt[n]);
    }
}

// ---------------- viterbi (single CTA, SMEM-resident backpointers) ---------
#define VIT_SMEM (NTAGS*NTAGS*4 + 2*96*4 + 16 + SEQ*NTAGS)

__global__ void viterbi_kernel(const float* __restrict__ trans, float* __restrict__ out,
                               int out_size) {
    extern __shared__ char smraw[];
    float* trs = (float*)smraw;                                   // 81*81
    float* fv  = (float*)(smraw + NTAGS * NTAGS * 4);             // 2*96 (double buffer)
    int*   sh_best = (int*)(smraw + NTAGS * NTAGS * 4 + 2 * 96 * 4);
    unsigned char* bp = (unsigned char*)(smraw + NTAGS * NTAGS * 4 + 2 * 96 * 4 + 16);
    int tid = threadIdx.x;

    for (int i = tid; i < NTAGS * NTAGS; i += 128) trs[i] = trans[i];
    if (tid < NTAGS) fv[tid] = (tid == START_TAG) ? 0.f : NEGV;
    __syncthreads();

    int cur = 0;
    for (int t = 0; t < SEQ; t++) {
        if (tid < NTAGS) {
            float feat = g_feats[t][tid];
            const float* tr = trs + tid * NTAGS;
            const float* f = fv + cur * 96;
            float b0 = -3.4e38f, b1 = -3.4e38f, b2 = -3.4e38f, b3 = -3.4e38f;
            int i0 = 0, i1 = 1, i2 = 2, i3 = 3;
#pragma unroll
            for (int j = 0; j < 80; j += 4) {
                float v0 = __fadd_rn(f[j], tr[j]);         if (v0 > b0) { b0 = v0; i0 = j; }
                float v1 = __fadd_rn(f[j + 1], tr[j + 1]); if (v1 > b1) { b1 = v1; i1 = j + 1; }
                float v2 = __fadd_rn(f[j + 2], tr[j + 2]); if (v2 > b2) { b2 = v2; i2 = j + 2; }
                float v3 = __fadd_rn(f[j + 3], tr[j + 3]); if (v3 > b3) { b3 = v3; i3 = j + 3; }
            }
            { float v = __fadd_rn(f[80], tr[80]); if (v > b0) { b0 = v; i0 = 80; } }
            // combine, first-index tie-break (matches jnp.argmax)
            float bb = b0; int bi = i0;
            if (b1 > bb || (b1 == bb && i1 < bi)) { bb = b1; bi = i1; }
            if (b2 > bb || (b2 == bb && i2 < bi)) { bb = b2; bi = i2; }
            if (b3 > bb || (b3 == bb && i3 < bi)) { bb = b3; bi = i3; }
            bp[t * NTAGS + tid] = (unsigned char)bi;
            float nv = __fadd_rn(bb, feat);
            fv[(cur ^ 1) * 96 + tid] = nv;
            g_fv2[t][tid] = nv;
        }
        __syncthreads();
        cur ^= 1;
    }

    if (tid == 0) {
        const float* f = fv + cur * 96;
        float best = -3.4e38f; int bi = 0;
        for (int i = 0; i < NTAGS; i++) {
            float v = __fadd_rn(f[i], trs[STOP_TAG * NTAGS + i]);
            if (v > best) { best = v; bi = i; }
        }
        if (out_size > 0) out[0] = best;       // path_score
        sh_best[0] = bi;
        int tag = bi;
        for (int t = SEQ - 1; t >= 0; t--) {   // backtrace in SMEM
            if (1 + t < out_size) out[1 + t] = (float)tag;
            tag = bp[t * NTAGS + tag];
        }
    }
    __syncthreads();
    int best = sh_best[0];
    for (int k = tid; k < SEQ; k += 128) {
        int idx = 1 + SEQ + k;
        if (idx < out_size) out[idx] = g_fv2[SEQ - 1 - k][best];  // best_tag_score
    }
}

// ---------------- launch -----------------------------------------------------
extern "C" void kernel_launch(void* const* d_in, const int* in_sizes, int n_in,
                              void* d_out, int out_size) {
    const int*   sentence = (const int*)d_in[0];
    const float* h0    = (const float*)d_in[1];
    const float* c0    = (const float*)d_in[2];
    const float* emb   = (const float*)d_in[3];
    const float* Wih_f = (const float*)d_in[4];
    const float* Whh_f = (const float*)d_in[5];
    const float* bih_f = (const float*)d_in[6];
    const float* bhh_f = (const float*)d_in[7];
    const float* Wih_b = (const float*)d_in[8];
    const float* Whh_b = (const float*)d_in[9];
    const float* bih_b = (const float*)d_in[10];
    const float* bhh_b = (const float*)d_in[11];
    const float* Wt    = (const float*)d_in[12];
    const float* bt    = (const float*)d_in[13];
    const float* trans = (const float*)d_in[14];
    float* out = (float*)d_out;

    reset_kernel<<<(2 * SEQ + 255) / 256, 256>>>();
    gather_kernel<<<SEQ, 128>>>(sentence, emb);
    lstm_kernel<<<REC_CTAS, 256>>>(h0, c0, Whh_f, Whh_b, Wih_f, Wih_b,
                                   bih_f, bhh_f, bih_b, bhh_b);
    feats_kernel<<<SEQ, 256>>>(Wt, bt);
    cudaFuncSetAttribute(viterbi_kernel, cudaFuncAttributeMaxDynamicSharedMemorySize, VIT_SMEM);
    viterbi_kernel<<<1, 128, VIT_SMEM>>>(trans, out, out_size);
}

// round 10
// speedup vs baseline: 1.2319x; 1.0575x over previous
#include <cuda_runtime.h>
#include <math.h>

#define Hd 512
#define SEQ 2048
#define NTAGS 81
#define START_TAG 79
#define STOP_TAG 80
#define NEGV -10000.0f
#define NCTA_DIR 64
#define REC_CTAS (2*NCTA_DIR)

// ---------------- scratch (device globals: no allocation allowed) ----------
__device__ float g_X[SEQ][Hd];           // gathered embeddings
__device__ float g_hseq[2][SEQ][Hd];     // hidden states
__device__ unsigned g_cnt[2][SEQ];       // per-step arrival counters (64 each)
__device__ float g_feats[SEQ][NTAGS];
__device__ float g_fv2[SEQ][NTAGS];      // viterbi step_vars history

// ---------------- reset (graph replays must be deterministic) --------------
__global__ void reset_kernel() {
    int i = blockIdx.x * blockDim.x + threadIdx.x;
    if (i < 2 * SEQ) ((unsigned*)g_cnt)[i] = 0u;
}

// ---------------- embedding gather -----------------------------------------
__global__ void gather_kernel(const int* __restrict__ sentence,
                              const float* __restrict__ emb) {
    int t = blockIdx.x;
    int idx = sentence[t];
    const float4* src = (const float4*)(emb + (size_t)idx * Hd);
    ((float4*)(g_X[t]))[threadIdx.x] = src[threadIdx.x];   // 128 * float4 = 512
}

// ---------------- recurrent LSTM (persistent, per-CTA release/acquire) -----
__device__ __forceinline__ unsigned ld_acq(const unsigned* p) {
    unsigned v;
    asm volatile("ld.acquire.gpu.global.u32 %0, [%1];" : "=r"(v) : "l"(p) : "memory");
    return v;
}
__device__ __forceinline__ void red_release(unsigned* p) {
    asm volatile("red.add.release.gpu.global.u32 [%0], 1;" :: "l"(p) : "memory");
}
__device__ __forceinline__ void st_cg_v4(float* p, float4 v) {
    asm volatile("st.global.cg.v4.f32 [%0], {%1,%2,%3,%4};"
                 :: "l"(p), "f"(v.x), "f"(v.y), "f"(v.z), "f"(v.w) : "memory");
}

__global__ __launch_bounds__(256, 1) void lstm_kernel(
    const float* __restrict__ h0, const float* __restrict__ c0,
    const float* __restrict__ Whh_f, const float* __restrict__ Whh_b,
    const float* __restrict__ Wih_f, const float* __restrict__ Wih_b,
    const float* __restrict__ bih_f, const float* __restrict__ bhh_f,
    const float* __restrict__ bih_b, const float* __restrict__ bhh_b) {
    int dir = (blockIdx.x >= NCTA_DIR) ? 1 : 0;
    int cta = blockIdx.x - dir * NCTA_DIR;
    const float* Whh = dir ? Whh_b : Whh_f;
    const float* Wih = dir ? Wih_b : Wih_f;
    const float* bih = dir ? bih_b : bih_f;
    const float* bhh = dir ? bhh_b : bhh_f;
    int warp = threadIdx.x >> 5, lane = threadIdx.x & 31;
    int tid = threadIdx.x;
    int unit = cta * 8 + warp;       // 8 warps, one hidden unit each

    // recurrent + input weights resident in registers (4 gate rows each)
    float wh0[16], wh1[16], wh2[16], wh3[16];
    float wx0[16], wx1[16], wx2[16], wx3[16];
    {
        const float* r0 = Whh + (size_t)unit * Hd;
        const float* r1 = Whh + (size_t)(unit + Hd) * Hd;
        const float* r2 = Whh + (size_t)(unit + 2 * Hd) * Hd;
        const float* r3 = Whh + (size_t)(unit + 3 * Hd) * Hd;
        const float* q0 = Wih + (size_t)unit * Hd;
        const float* q1 = Wih + (size_t)(unit + Hd) * Hd;
        const float* q2 = Wih + (size_t)(unit + 2 * Hd) * Hd;
        const float* q3 = Wih + (size_t)(unit + 3 * Hd) * Hd;
#pragma unroll
        for (int k = 0; k < 16; k++) {
            wh0[k] = r0[k * 32 + lane];
            wh1[k] = r1[k * 32 + lane];
            wh2[k] = r2[k * 32 + lane];
            wh3[k] = r3[k * 32 + lane];
            wx0[k] = q0[k * 32 + lane];
            wx1[k] = q1[k * 32 + lane];
            wx2[k] = q2[k * 32 + lane];
            wx3[k] = q3[k * 32 + lane];
        }
    }

    float bi0 = 0.f, bi1 = 0.f, bi2 = 0.f, bi3 = 0.f;
    float bh0 = 0.f, bh1 = 0.f, bh2 = 0.f, bh3 = 0.f;
    float c = 0.f;
    if (lane == 0) {
        bi0 = bih[unit];            bh0 = bhh[unit];
        bi1 = bih[unit + Hd];       bh1 = bhh[unit + Hd];
        bi2 = bih[unit + 2 * Hd];   bh2 = bhh[unit + 2 * Hd];
        bi3 = bih[unit + 3 * Hd];   bh3 = bhh[unit + 3 * Hd];
        c = c0[dir * Hd + unit];
    }

    __shared__ float h_sh[Hd];
    __shared__ __align__(16) float h8[8];   // this CTA's 8 fresh h values

    for (int s = 0; s < SEQ; s++) {
        int t = dir ? (SEQ - 1 - s) : s;

        // ---- u = x_t · Wih rows (before the poll: hides in store flight)
        float u0 = 0.f, u1 = 0.f, u2 = 0.f, u3 = 0.f;
        {
            const float* xp = &g_X[t][0];
#pragma unroll
            for (int k = 0; k < 16; k++) {
                float xv = __ldg(xp + k * 32 + lane);
                u0 += wx0[k] * xv;
                u1 += wx1[k] * xv;
                u2 += wx2[k] * xv;
                u3 += wx3[k] * xv;
            }
#pragma unroll
            for (int off = 16; off > 0; off >>= 1) {
                u0 += __shfl_xor_sync(0xffffffffu, u0, off);
                u1 += __shfl_xor_sync(0xffffffffu, u1, off);
                u2 += __shfl_xor_sync(0xffffffffu, u2, off);
                u3 += __shfl_xor_sync(0xffffffffu, u3, off);
            }
        }

        // ---- acquire h_{t-1}: single poller + morally-strong CTA barrier
        const float* hsrc;
        if (s == 0) {
            hsrc = h0 + dir * Hd;
        } else {
            int tp = dir ? t + 1 : t - 1;
            if (tid == 0) {
                const unsigned* cp = &g_cnt[dir][tp];
                while (ld_acq(cp) < NCTA_DIR) {}
            }
            hsrc = &g_hseq[dir][tp][0];
        }
        // bar1: publishes poller's acquire to all threads (transitive causality)
        // and separates previous step's h_sh readers from the overwrite below
        __syncthreads();
        h_sh[tid]       = __ldcg(&hsrc[tid]);   // L2 path only
        h_sh[tid + 256] = __ldcg(&hsrc[tid + 256]);
        __syncthreads();                        // bar2

        // ---- a = h_{t-1} · Whh rows
        float a0 = 0.f, a1 = 0.f, a2 = 0.f, a3 = 0.f;
#pragma unroll
        for (int k = 0; k < 16; k++) {
            float hv = h_sh[k * 32 + lane];
            a0 += wh0[k] * hv;
            a1 += wh1[k] * hv;
            a2 += wh2[k] * hv;
            a3 += wh3[k] * hv;
        }
#pragma unroll
        for (int off = 16; off > 0; off >>= 1) {
            a0 += __shfl_xor_sync(0xffffffffu, a0, off);
            a1 += __shfl_xor_sync(0xffffffffu, a1, off);
            a2 += __shfl_xor_sync(0xffffffffu, a2, off);
            a3 += __shfl_xor_sync(0xffffffffu, a3, off);
        }
        if (lane == 0) {
            // g = ((xW + hW) + bih) + bhh  -- reference add order, no FMA fusion
            float gi = __fadd_rn(__fadd_rn(__fadd_rn(u0, a0), bi0), bh0);
            float gf = __fadd_rn(__fadd_rn(__fadd_rn(u1, a1), bi1), bh1);
            float gg = __fadd_rn(__fadd_rn(__fadd_rn(u2, a2), bi2), bh2);
            float go = __fadd_rn(__fadd_rn(__fadd_rn(u3, a3), bi3), bh3);
            float i_ = 1.f / (1.f + expf(-gi));
            float f_ = 1.f / (1.f + expf(-gf));
            float o_ = 1.f / (1.f + expf(-go));
            c = __fadd_rn(__fmul_rn(f_, c), __fmul_rn(i_, tanhf(gg)));
            float h2 = __fmul_rn(o_, tanhf(c));
            h8[warp] = h2;                      // stage in SMEM
        }
        __syncthreads();                        // bar3: h8 complete
        if (tid == 0) {
            // single thread stores the CTA's whole h block, then releases:
            // same-thread st.cg -> red.release ordering is airtight
            float4 v0 = *(float4*)&h8[0];
            float4 v1 = *(float4*)&h8[4];
            float* dst = &g_hseq[dir][t][cta * 8];
            st_cg_v4(dst, v0);
            st_cg_v4(dst + 4, v1);
            red_release(&g_cnt[dir][t]);
        }
        // h8 reuse next step is safe: rewritten only after next bar2 > bar3
    }
}

// ---------------- feats: concat(hf,hb) @ Wt^T + bt (fp32) -------------------
__global__ __launch_bounds__(256) void feats_kernel(const float* __restrict__ Wt,
                                                    const float* __restrict__ bt) {
    int t = blockIdx.x;
    __shared__ float hc[2 * Hd];
    int tid = threadIdx.x;
#pragma unroll
    for (int i = 0; i < 4; i++) {
        int j = tid + i * 256;
        hc[j] = (j < Hd) ? g_hseq[0][t][j] : g_hseq[1][t][j - Hd];
    }
    __syncthreads();
    int warp = tid >> 5, lane = tid & 31;
    for (int n = warp; n < NTAGS; n += 8) {
        const float* w = Wt + (size_t)n * 2 * Hd;
        float s = 0.f;
#pragma unroll
        for (int k = lane; k < 2 * Hd; k += 32) s += w[k] * hc[k];
#pragma unroll
        for (int off = 16; off > 0; off >>= 1) s += __shfl_xor_sync(0xffffffffu, s, off);
        if (lane == 0) g_feats[t][n] = __fadd_rn(s, bt[n]);
    }
}

// ---------------- viterbi (single CTA, SMEM-resident backpointers) ---------
#define VIT_SMEM (NTAGS*NTAGS*4 + 2*96*4 + 16 + SEQ*NTAGS)

__global__ void viterbi_kernel(const float* __restrict__ trans, float* __restrict__ out,
                               int out_size) {
    extern __shared__ char smraw[];
    float* trs = (float*)smraw;                                   // 81*81
    float* fv  = (float*)(smraw + NTAGS * NTAGS * 4);             // 2*96 (double buffer)
    int*   sh_best = (int*)(smraw + NTAGS * NTAGS * 4 + 2 * 96 * 4);
    unsigned char* bp = (unsigned char*)(smraw + NTAGS * NTAGS * 4 + 2 * 96 * 4 + 16);
    int tid = threadIdx.x;

    for (int i = tid; i < NTAGS * NTAGS; i += 128) trs[i] = trans[i];
    if (tid < NTAGS) fv[tid] = (tid == START_TAG) ? 0.f : NEGV;
    __syncthreads();

    int cur = 0;
    for (int t = 0; t < SEQ; t++) {
        if (tid < NTAGS) {
            float feat = g_feats[t][tid];
            const float* tr = trs + tid * NTAGS;
            const float* f = fv + cur * 96;
            float b0 = -3.4e38f, b1 = -3.4e38f, b2 = -3.4e38f, b3 = -3.4e38f;
            int i0 = 0, i1 = 1, i2 = 2, i3 = 3;
#pragma unroll
            for (int j = 0; j < 80; j += 4) {
                float v0 = __fadd_rn(f[j], tr[j]);         if (v0 > b0) { b0 = v0; i0 = j; }
                float v1 = __fadd_rn(f[j + 1], tr[j + 1]); if (v1 > b1) { b1 = v1; i1 = j + 1; }
                float v2 = __fadd_rn(f[j + 2], tr[j + 2]); if (v2 > b2) { b2 = v2; i2 = j + 2; }
                float v3 = __fadd_rn(f[j + 3], tr[j + 3]); if (v3 > b3) { b3 = v3; i3 = j + 3; }
            }
            { float v = __fadd_rn(f[80], tr[80]); if (v > b0) { b0 = v; i0 = 80; } }
            // combine, first-index tie-break (matches jnp.argmax)
            float bb = b0; int bi = i0;
            if (b1 > bb || (b1 == bb && i1 < bi)) { bb = b1; bi = i1; }
            if (b2 > bb || (b2 == bb && i2 < bi)) { bb = b2; bi = i2; }
            if (b3 > bb || (b3 == bb && i3 < bi)) { bb = b3; bi = i3; }
            bp[t * NTAGS + tid] = (unsigned char)bi;
            float nv = __fadd_rn(bb, feat);
            fv[(cur ^ 1) * 96 + tid] = nv;
            g_fv2[t][tid] = nv;
        }
        __syncthreads();
        cur ^= 1;
    }

    if (tid == 0) {
        const float* f = fv + cur * 96;
        float best = -3.4e38f; int bi = 0;
        for (int i = 0; i < NTAGS; i++) {
            float v = __fadd_rn(f[i], trs[STOP_TAG * NTAGS + i]);
            if (v > best) { best = v; bi = i; }
        }
        if (out_size > 0) out[0] = best;       // path_score
        sh_best[0] = bi;
        int tag = bi;
        for (int t = SEQ - 1; t >= 0; t--) {   // backtrace in SMEM
            if (1 + t < out_size) out[1 + t] = (float)tag;
            tag = bp[t * NTAGS + tag];
        }
    }
    __syncthreads();
    int best = sh_best[0];
    for (int k = tid; k < SEQ; k += 128) {
        int idx = 1 + SEQ + k;
        if (idx < out_size) out[idx] = g_fv2[SEQ - 1 - k][best];  // best_tag_score
    }
}

// ---------------- launch -----------------------------------------------------
extern "C" void kernel_launch(void* const* d_in, const int* in_sizes, int n_in,
                              void* d_out, int out_size) {
    const int*   sentence = (const int*)d_in[0];
    const float* h0    = (const float*)d_in[1];
    const float* c0    = (const float*)d_in[2];
    const float* emb   = (const float*)d_in[3];
    const float* Wih_f = (const float*)d_in[4];
    const float* Whh_f = (const float*)d_in[5];
    const float* bih_f = (const float*)d_in[6];
    const float* bhh_f = (const float*)d_in[7];
    const float* Wih_b = (const float*)d_in[8];
    const float* Whh_b = (const float*)d_in[9];
    const float* bih_b = (const float*)d_in[10];
    const float* bhh_b = (const float*)d_in[11];
    const float* Wt    = (const float*)d_in[12];
    const float* bt    = (const float*)d_in[13];
    const float* trans = (const float*)d_in[14];
    float* out = (float*)d_out;

    reset_kernel<<<(2 * SEQ + 255) / 256, 256>>>();
    gather_kernel<<<SEQ, 128>>>(sentence, emb);
    lstm_kernel<<<REC_CTAS, 256>>>(h0, c0, Whh_f, Whh_b, Wih_f, Wih_b,
                                   bih_f, bhh_f, bih_b, bhh_b);
    feats_kernel<<<SEQ, 256>>>(Wt, bt);
    cudaFuncSetAttribute(viterbi_kernel, cudaFuncAttributeMaxDynamicSharedMemorySize, VIT_SMEM);
    viterbi_kernel<<<1, 128, VIT_SMEM>>>(trans, out, out_size);
}